// round 13
// baseline (speedup 1.0000x reference)
#include <cuda_runtime.h>
#include <cuda_fp16.h>
#include <math.h>
#include <stdint.h>

#define NT 256
#define RB 32

// smem byte offsets (single weight region; 2 CTAs/SM)
#define AH_OFF   0
#define AL_OFF   8704
#define WH_OFF   17408
#define WL_OFF   52224
#define U16_OFF  87040           // u as fp16 [3][32][128] = 24576 B
#define SM_TOTAL 111616

// pre-split padded weights: 7 tiles of [128 n][136 k] halves
// tiles: 0=U, 1=V, 2=W1[:, :128], 3=W1[:, 128:], 4..6=W2 row-chunks
__device__ __align__(16) __half g_wh[7 * 128 * 136];
__device__ __align__(16) __half g_wl[7 * 128 * 136];

__device__ __forceinline__ uint32_t s2u(const void* p) {
    uint32_t a;
    asm("{ .reg .u64 t; cvta.to.shared.u64 t, %1; cvt.u32.u64 %0, t; }" : "=r"(a) : "l"(p));
    return a;
}

#define LDSM4(d, a) \
    asm volatile("ldmatrix.sync.aligned.m8n8.x4.shared.b16 {%0,%1,%2,%3}, [%4];" \
                 : "=r"((d)[0]), "=r"((d)[1]), "=r"((d)[2]), "=r"((d)[3]) : "r"(a))

__device__ __forceinline__ void mma_16816(float* d, const uint32_t a[4],
                                          uint32_t b0, uint32_t b1) {
    asm volatile(
        "mma.sync.aligned.m16n8k16.row.col.f32.f16.f16.f32 "
        "{%0,%1,%2,%3}, {%4,%5,%6,%7}, {%8,%9}, {%0,%1,%2,%3};"
        : "+f"(d[0]), "+f"(d[1]), "+f"(d[2]), "+f"(d[3])
        : "r"(a[0]), "r"(a[1]), "r"(a[2]), "r"(a[3]), "r"(b0), "r"(b1));
}

__device__ __forceinline__ void cp16(uint32_t dst, const void* src) {
    asm volatile("cp.async.cg.shared.global [%0], [%1], 16;"
                 :: "r"(dst), "l"(src) : "memory");
}
#define CP_COMMIT() asm volatile("cp.async.commit_group;" ::: "memory")
#define CP_WAIT0()  asm volatile("cp.async.wait_group 0;" ::: "memory")

// K=128 GEMM: acc (+)= A x B, fp32-emulated in 3 fp16 passes (hh + hl + lh)
__device__ __forceinline__ void gemm_go(float* acc,
                                        uint32_t aH0, uint32_t aH1,
                                        uint32_t aL0, uint32_t aL1,
                                        uint32_t bH, uint32_t bL) {
#pragma unroll
    for (int k0 = 0; k0 < 128; k0 += 16) {
        const uint32_t ko = (uint32_t)k0 * 2;
        uint32_t fah[2][4], fal[2][4], fbh[4], fbl[4];
        LDSM4(fah[0], aH0 + ko);
        LDSM4(fah[1], aH1 + ko);
        LDSM4(fal[0], aL0 + ko);
        LDSM4(fal[1], aL1 + ko);
        LDSM4(fbh, bH + ko);
        LDSM4(fbl, bL + ko);
#pragma unroll
        for (int mt = 0; mt < 2; mt++)
#pragma unroll
            for (int nt = 0; nt < 2; nt++) {
                float* d = acc + mt * 8 + nt * 4;
                mma_16816(d, fah[mt], fbh[nt * 2], fbh[nt * 2 + 1]);
                mma_16816(d, fah[mt], fbl[nt * 2], fbl[nt * 2 + 1]);
                mma_16816(d, fal[mt], fbh[nt * 2], fbh[nt * 2 + 1]);
            }
    }
}

__device__ __forceinline__ void put_hl(__half* H, __half* L, int off, float x) {
    __half h = __float2half_rn(x);
    H[off] = h;
    L[off] = __float2half_rn(x - __half2float(h));
}

// ---------------------------------------------------------------------------
__global__ void prep_kernel(const float* __restrict__ U, const float* __restrict__ V,
                            const float* __restrict__ W1, const float* __restrict__ W2) {
    int idx = blockIdx.x * blockDim.x + threadIdx.x;
    if (idx >= 7 * 16384) return;
    int t = idx >> 14;
    int n = (idx >> 7) & 127;
    int k = idx & 127;
    float val;
    if (t == 0)      val = U[n * 128 + k];
    else if (t == 1) val = V[n * 128 + k];
    else if (t == 2) val = W1[n * 256 + k];
    else if (t == 3) val = W1[n * 256 + 128 + k];
    else             val = W2[((t - 4) * 128 + n) * 128 + k];
    __half h = __float2half_rn(val);
    __half l = __float2half_rn(val - __half2float(h));
    g_wh[t * 17408 + n * 136 + k] = h;
    g_wl[t * 17408 + n * 136 + k] = l;
}

// ---------------------------------------------------------------------------
__global__ __launch_bounds__(NT, 2)
void update_mma_kernel(const float* __restrict__ vec, const float* __restrict__ sca,
                       const float* __restrict__ b1g, const float* __restrict__ b2g,
                       float* __restrict__ out, int nrows) {
    extern __shared__ char sm[];
    const uint32_t smb = s2u(sm);
    __half* Ah = (__half*)(sm + AH_OFF);
    __half* Al = (__half*)(sm + AL_OFF);
    __half* Uh = (__half*)(sm + U16_OFF);  // [3][32][128] fp16

    const int tid = threadIdx.x;
    const int lane = tid & 31;
    const int wn = tid >> 5;   // N band (0..7)
    const int row0 = blockIdx.x * RB;

    // ldmatrix per-thread byte offsets (within a [.][136]-half region)
    const uint32_t aoff0 = (((lane & 7) + ((lane >> 3) & 1) * 8) * 136
                            + ((lane >> 4) & 1) * 8) * 2;
    const uint32_t aoff1 = aoff0 + 16 * 136 * 2;
    const uint32_t boff  = ((wn * 16 + ((lane >> 4) & 1) * 8 + (lane & 7)) * 136
                            + ((lane >> 3) & 1) * 8) * 2;

    const uint32_t AHb = smb + AH_OFF, ALb = smb + AL_OFF;
    const uint32_t BH = smb + WH_OFF + boff, BL = smb + WL_OFF + boff;

    // fragment ownership bases
    const int rbase = lane >> 2;            // + mt*16 + (jj>>1)*8  -> 0..31
    const int cbase = wn * 16 + (lane & 3) * 2;

#define POS_LOOP(body) \
    _Pragma("unroll") for (int mt = 0; mt < 2; mt++) \
    _Pragma("unroll") for (int nt = 0; nt < 2; nt++) \
    _Pragma("unroll") for (int jj = 0; jj < 4; jj++) { \
        const int idx = mt * 8 + nt * 4 + jj; \
        const int row = rbase + mt * 16 + (jj >> 1) * 8; \
        const int col = cbase + nt * 8 + (jj & 1); \
        body \
    }

    // weight tile t -> the single W region (hi+lo), via cp.async (one group)
    auto cpa_w = [&](int t) {
        const uint4* sh = (const uint4*)(g_wh + t * 17408);
        const uint4* sl = (const uint4*)(g_wl + t * 17408);
        for (int i = tid; i < 2176; i += NT) {
            cp16(smb + WH_OFF + i * 16, sh + i);
            cp16(smb + WL_OFF + i * 16, sl + i);
        }
        CP_COMMIT();
    };
    auto stage_a_vec = [&](int i) {
        for (int e = tid; e < RB * 128; e += NT) {
            int r = e >> 7, c = e & 127;
            float x = __ldg(vec + (size_t)(row0 + r) * 384 + c * 3 + i);
            put_hl(Ah, Al, r * 136 + c, x);
        }
    };

    // ---- phase 1a: u_i = X_i @ U^T, stash to Uh ----
    cpa_w(0);                          // U
    stage_a_vec(0);
    CP_WAIT0();
    __syncthreads();
    for (int i = 0; i < 3; i++) {
        float uacc[16];
#pragma unroll
        for (int j = 0; j < 16; j++) uacc[j] = 0.0f;
        gemm_go(uacc, AHb + aoff0, AHb + aoff1, ALb + aoff0, ALb + aoff1, BH, BL);
        POS_LOOP( Uh[(i << 12) + (row << 7) + col] = __float2half_rn(uacc[idx]); )
        if (i < 2) {
            __syncthreads();
            stage_a_vec(i + 1);
            __syncthreads();
        }
    }
    __syncthreads();                   // U region dead

    // ---- phase 1b: v_i = X_i @ V^T; fold ssq, dot (u from Uh) ----
    cpa_w(1);                          // V
    stage_a_vec(0);
    CP_WAIT0();
    __syncthreads();
    float dotv[16], ssq[16];
#pragma unroll
    for (int j = 0; j < 16; j++) { dotv[j] = 0.0f; ssq[j] = 1e-8f; }
    for (int i = 0; i < 3; i++) {
        float vacc[16];
#pragma unroll
        for (int j = 0; j < 16; j++) vacc[j] = 0.0f;
        gemm_go(vacc, AHb + aoff0, AHb + aoff1, ALb + aoff0, ALb + aoff1, BH, BL);
        POS_LOOP(
            float vv = vacc[idx];
            float uu = __half2float(Uh[(i << 12) + (row << 7) + col]);
            ssq[idx]  += vv * vv;
            dotv[idx] += uu * vv;
        )
        if (i < 2) {
            __syncthreads();
            stage_a_vec(i + 1);
            __syncthreads();
        }
    }
    __syncthreads();                   // V dead

    // ---- phase 2: h = silu([s|vnorm] @ W1^T + b1) ----
    cpa_w(2);                          // W1a
    for (int e = tid; e < RB * 128; e += NT) {   // A = scalar tile
        int r = e >> 7, c = e & 127;
        put_hl(Ah, Al, r * 136 + c, __ldg(sca + (size_t)(row0 + r) * 128 + c));
    }
    CP_WAIT0();
    __syncthreads();
    float hacc[16];
#pragma unroll
    for (int j = 0; j < 16; j++) hacc[j] = 0.0f;
    gemm_go(hacc, AHb + aoff0, AHb + aoff1, ALb + aoff0, ALb + aoff1, BH, BL);
    __syncthreads();                   // A + W1a dead
    cpa_w(3);                          // W1b
    POS_LOOP( put_hl(Ah, Al, row * 136 + col, sqrtf(ssq[idx])); )   // A = vnorm
    CP_WAIT0();
    __syncthreads();
    gemm_go(hacc, AHb + aoff0, AHb + aoff1, ALb + aoff0, ALb + aoff1, BH, BL);
    __syncthreads();                   // A + W1b dead
    cpa_w(4);                          // W2a
    POS_LOOP(                          // A = silu(h + b1)
        float x = hacc[idx] + __ldg(b1g + col);
        put_hl(Ah, Al, row * 136 + col, x / (1.0f + __expf(-x)));
    )
    CP_WAIT0();
    __syncthreads();

    // ---- phase 3: a, b, c chunks ----
    float aacc[16];
#pragma unroll
    for (int j = 0; j < 16; j++) aacc[j] = 0.0f;
    gemm_go(aacc, AHb + aoff0, AHb + aoff1, ALb + aoff0, ALb + aoff1, BH, BL);
    float av[16];
    POS_LOOP( av[idx] = aacc[idx] + __ldg(b2g + col); )
    __syncthreads();                   // W2a dead
    cpa_w(5);                          // W2b
    CP_WAIT0();
    __syncthreads();
    float bacc[16];
#pragma unroll
    for (int j = 0; j < 16; j++) bacc[j] = 0.0f;
    gemm_go(bacc, AHb + aoff0, AHb + aoff1, ALb + aoff0, ALb + aoff1, BH, BL);
    float bv[16];
    POS_LOOP( bv[idx] = bacc[idx] + __ldg(b2g + 128 + col); )
    __syncthreads();                   // W2b dead
    cpa_w(6);                          // W2c
    CP_WAIT0();
    __syncthreads();
    float cacc[16];
#pragma unroll
    for (int j = 0; j < 16; j++) cacc[j] = 0.0f;
    gemm_go(cacc, AHb + aoff0, AHb + aoff1, ALb + aoff0, ALb + aoff1, BH, BL);

    // ---- epilogue: direct global writes from fragment owners ----
    // delta_s = b + c*dot  (float2, 8B-aligned)
    {
        float* out_ds = out + (size_t)nrows * 384;
#pragma unroll
        for (int mt = 0; mt < 2; mt++)
#pragma unroll
            for (int nt = 0; nt < 2; nt++)
#pragma unroll
                for (int j2 = 0; j2 < 2; j2++) {
                    const int i0 = mt * 8 + nt * 4 + j2 * 2;
                    const int row = rbase + mt * 16 + j2 * 8;
                    const int c = cbase + nt * 8;
                    float c0 = cacc[i0]     + __ldg(b2g + 256 + c);
                    float c1 = cacc[i0 + 1] + __ldg(b2g + 256 + c + 1);
                    float2 d = make_float2(bv[i0] + c0 * dotv[i0],
                                           bv[i0 + 1] + c1 * dotv[i0 + 1]);
                    *(float2*)(out_ds + (size_t)(row0 + row) * 128 + c) = d;
                }
    }
    // delta_v = u16 * a  (3x float2 per (row, col-pair))
#pragma unroll
    for (int mt = 0; mt < 2; mt++)
#pragma unroll
        for (int nt = 0; nt < 2; nt++)
#pragma unroll
            for (int j2 = 0; j2 < 2; j2++) {
                const int i0 = mt * 8 + nt * 4 + j2 * 2;
                const int row = rbase + mt * 16 + j2 * 8;
                const int c = cbase + nt * 8;
                float a0 = av[i0], a1 = av[i0 + 1];
                float u0c = __half2float(Uh[(0 << 12) + (row << 7) + c]);
                float u1c = __half2float(Uh[(1 << 12) + (row << 7) + c]);
                float u2c = __half2float(Uh[(2 << 12) + (row << 7) + c]);
                float u0d = __half2float(Uh[(0 << 12) + (row << 7) + c + 1]);
                float u1d = __half2float(Uh[(1 << 12) + (row << 7) + c + 1]);
                float u2d = __half2float(Uh[(2 << 12) + (row << 7) + c + 1]);
                float* op = out + (size_t)(row0 + row) * 384 + (size_t)c * 3;
                ((float2*)op)[0] = make_float2(u0c * a0, u1c * a0);
                ((float2*)op)[1] = make_float2(u2c * a0, u0d * a1);
                ((float2*)op)[2] = make_float2(u1d * a1, u2d * a1);
            }
#undef POS_LOOP
}

// ---------------------------------------------------------------------------
extern "C" void kernel_launch(void* const* d_in, const int* in_sizes, int n_in,
                              void* d_out, int out_size) {
    const float* vec = (const float*)d_in[0];  // [N, C, 3]
    const float* sca = (const float*)d_in[1];  // [N, C]
    const float* U   = (const float*)d_in[2];  // [C, C]
    const float* V   = (const float*)d_in[3];  // [C, C]
    const float* W1  = (const float*)d_in[4];  // [C, 2C]
    const float* b1  = (const float*)d_in[5];  // [C]
    const float* W2  = (const float*)d_in[6];  // [3C, C]
    const float* b2  = (const float*)d_in[7];  // [3C]
    float* out = (float*)d_out;

    int nrows = in_sizes[0] / 384;
    int nblocks = nrows / RB;

    prep_kernel<<<448, 256>>>(U, V, W1, W2);

    cudaFuncSetAttribute(update_mma_kernel,
                         cudaFuncAttributeMaxDynamicSharedMemorySize, SM_TOTAL);
    update_mma_kernel<<<nblocks, NT, SM_TOTAL>>>(vec, sca, b1, b2, out, nrows);
}

// round 14
// speedup vs baseline: 1.6398x; 1.6398x over previous
#include <cuda_runtime.h>
#include <cuda_fp16.h>
#include <math.h>
#include <stdint.h>

#define NT 512
#define RB 64

// smem byte offsets
#define AH_OFF   0          // A hi [64][136] fp16
#define AL_OFF   17408      // A lo
#define W0_OFF   34816      // weight hi-only [128][136] fp16
#define W1_OFF   69632
#define UF_OFF   104448     // u fp32 [3][64][128] = 98304 B
#define SM_TOTAL 202752

// pre-rounded padded weights (hi only): 7 tiles of [128 n][136 k] fp16
// tiles: 0=U, 1=V, 2=W1[:, :128], 3=W1[:, 128:], 4..6=W2 row-chunks
__device__ __align__(16) __half g_wh[7 * 128 * 136];

__device__ __forceinline__ uint32_t s2u(const void* p) {
    uint32_t a;
    asm("{ .reg .u64 t; cvta.to.shared.u64 t, %1; cvt.u32.u64 %0, t; }" : "=r"(a) : "l"(p));
    return a;
}

#define LDSM4(d, a) \
    asm volatile("ldmatrix.sync.aligned.m8n8.x4.shared.b16 {%0,%1,%2,%3}, [%4];" \
                 : "=r"((d)[0]), "=r"((d)[1]), "=r"((d)[2]), "=r"((d)[3]) : "r"(a))

__device__ __forceinline__ void mma_16816(float* d, const uint32_t a[4],
                                          uint32_t b0, uint32_t b1) {
    asm volatile(
        "mma.sync.aligned.m16n8k16.row.col.f32.f16.f16.f32 "
        "{%0,%1,%2,%3}, {%4,%5,%6,%7}, {%8,%9}, {%0,%1,%2,%3};"
        : "+f"(d[0]), "+f"(d[1]), "+f"(d[2]), "+f"(d[3])
        : "r"(a[0]), "r"(a[1]), "r"(a[2]), "r"(a[3]), "r"(b0), "r"(b1));
}

__device__ __forceinline__ void cp16(uint32_t dst, const void* src) {
    asm volatile("cp.async.cg.shared.global [%0], [%1], 16;"
                 :: "r"(dst), "l"(src) : "memory");
}
#define CP_COMMIT() asm volatile("cp.async.commit_group;" ::: "memory")
#define CP_WAIT0()  asm volatile("cp.async.wait_group 0;" ::: "memory")
#define CP_WAIT1()  asm volatile("cp.async.wait_group 1;" ::: "memory")

// K=128 GEMM, 2-pass fp32-emulation: acc (+)= (Ah + Al) x Bh
// optional second B (dual) sharing the A fragments.
template <bool DUAL>
__device__ __forceinline__ void gemm2(float* acc0, float* acc1,
                                      uint32_t aH0, uint32_t aH1,
                                      uint32_t aL0, uint32_t aL1,
                                      uint32_t b0, uint32_t b1) {
#pragma unroll
    for (int k0 = 0; k0 < 128; k0 += 16) {
        const uint32_t ko = (uint32_t)k0 * 2;
        uint32_t fah[2][4], fal[2][4], fb0[4];
        LDSM4(fah[0], aH0 + ko);
        LDSM4(fah[1], aH1 + ko);
        LDSM4(fal[0], aL0 + ko);
        LDSM4(fal[1], aL1 + ko);
        LDSM4(fb0, b0 + ko);
#pragma unroll
        for (int mt = 0; mt < 2; mt++)
#pragma unroll
            for (int nt = 0; nt < 2; nt++) {
                float* d = acc0 + mt * 8 + nt * 4;
                mma_16816(d, fah[mt], fb0[nt * 2], fb0[nt * 2 + 1]);
                mma_16816(d, fal[mt], fb0[nt * 2], fb0[nt * 2 + 1]);
            }
        if (DUAL) {
            uint32_t fb1[4];
            LDSM4(fb1, b1 + ko);
#pragma unroll
            for (int mt = 0; mt < 2; mt++)
#pragma unroll
                for (int nt = 0; nt < 2; nt++) {
                    float* d = acc1 + mt * 8 + nt * 4;
                    mma_16816(d, fah[mt], fb1[nt * 2], fb1[nt * 2 + 1]);
                    mma_16816(d, fal[mt], fb1[nt * 2], fb1[nt * 2 + 1]);
                }
        }
    }
}

__device__ __forceinline__ void put_hl(__half* H, __half* L, int off, float x) {
    __half h = __float2half_rn(x);
    H[off] = h;
    L[off] = __float2half_rn(x - __half2float(h));
}

// ---------------------------------------------------------------------------
__global__ void prep_kernel(const float* __restrict__ U, const float* __restrict__ V,
                            const float* __restrict__ W1, const float* __restrict__ W2) {
    int idx = blockIdx.x * blockDim.x + threadIdx.x;
    if (idx >= 7 * 16384) return;
    int t = idx >> 14;
    int n = (idx >> 7) & 127;
    int k = idx & 127;
    float val;
    if (t == 0)      val = U[n * 128 + k];
    else if (t == 1) val = V[n * 128 + k];
    else if (t == 2) val = W1[n * 256 + k];
    else if (t == 3) val = W1[n * 256 + 128 + k];
    else             val = W2[((t - 4) * 128 + n) * 128 + k];
    g_wh[t * 17408 + n * 136 + k] = __float2half_rn(val);
}

// ---------------------------------------------------------------------------
__global__ __launch_bounds__(NT, 1)
void update_mma_kernel(const float* __restrict__ vec, const float* __restrict__ sca,
                       const float* __restrict__ b1g, const float* __restrict__ b2g,
                       float* __restrict__ out, int nrows) {
    extern __shared__ char sm[];
    const uint32_t smb = s2u(sm);
    __half* Ah = (__half*)(sm + AH_OFF);
    __half* Al = (__half*)(sm + AL_OFF);
    float*  Uf = (float*)(sm + UF_OFF);  // u fp32 [3][64][128]

    const int tid = threadIdx.x;
    const int lane = tid & 31;
    const int w = tid >> 5;
    const int wm = w & 1;    // M band (0/1)
    const int wn = w >> 1;   // N band (0..7)
    const int row0 = blockIdx.x * RB;

    // ldmatrix per-thread byte offsets (within a [.][136]-half region)
    const uint32_t aoff0 = ((wm * 32 + (lane & 7) + ((lane >> 3) & 1) * 8) * 136
                            + ((lane >> 4) & 1) * 8) * 2;
    const uint32_t aoff1 = aoff0 + 16 * 136 * 2;
    const uint32_t boff  = ((wn * 16 + ((lane >> 4) & 1) * 8 + (lane & 7)) * 136
                            + ((lane >> 3) & 1) * 8) * 2;

    const uint32_t AH0 = smb + AH_OFF + aoff0, AH1 = smb + AH_OFF + aoff1;
    const uint32_t AL0 = smb + AL_OFF + aoff0, AL1 = smb + AL_OFF + aoff1;
    const uint32_t B0 = smb + W0_OFF + boff, B1 = smb + W1_OFF + boff;

    // fragment ownership bases
    const int rbase = wm * 32 + (lane >> 2);
    const int cbase = wn * 16 + (lane & 3) * 2;

#define POS_LOOP(body) \
    _Pragma("unroll") for (int mt = 0; mt < 2; mt++) \
    _Pragma("unroll") for (int nt = 0; nt < 2; nt++) \
    _Pragma("unroll") for (int jj = 0; jj < 4; jj++) { \
        const int idx = mt * 8 + nt * 4 + jj; \
        const int row = rbase + mt * 16 + (jj >> 1) * 8; \
        const int col = cbase + nt * 8 + (jj & 1); \
        body \
    }

    // weight tile t (hi only, 34816 B) -> region, one cp.async group
    auto cpa_w = [&](uint32_t dstOff, int t) {
        const uint4* sh = (const uint4*)(g_wh + t * 17408);
        for (int i = tid; i < 2176; i += NT) cp16(smb + dstOff + i * 16, sh + i);
        CP_COMMIT();
    };

    float pf[16];
    auto prefetch_vec = [&](int i) {
#pragma unroll
        for (int q = 0; q < 16; q++) {
            int e = tid + q * NT;
            int r = e >> 7, c = e & 127;
            pf[q] = __ldg(vec + (size_t)(row0 + r) * 384 + c * 3 + i);
        }
    };
    auto prefetch_sca = [&]() {
#pragma unroll
        for (int q = 0; q < 16; q++) {
            int e = tid + q * NT;
            int r = e >> 7, c = e & 127;
            pf[q] = __ldg(sca + (size_t)(row0 + r) * 128 + c);
        }
    };
    auto sts_pf = [&]() {
#pragma unroll
        for (int q = 0; q < 16; q++) {
            int e = tid + q * NT;
            int r = e >> 7, c = e & 127;
            put_hl(Ah, Al, r * 136 + c, pf[q]);
        }
    };

    // ---- init: weights U,V in flight; X0 staged ----
    prefetch_vec(0);
    cpa_w(W0_OFF, 0);   // G0: U
    cpa_w(W1_OFF, 1);   // G1: V
    sts_pf();
    CP_WAIT0();
    __syncthreads();

    // ---- phase 1: u,v per component (dual 2-pass); fold; u -> Uf (fp32) ----
    float dotv[16], ssq[16];
#pragma unroll
    for (int j = 0; j < 16; j++) { dotv[j] = 0.0f; ssq[j] = 1e-8f; }

    for (int i = 0; i < 3; i++) {
        if (i < 2) prefetch_vec(i + 1);
        else       prefetch_sca();
        float uacc[16], vacc[16];
#pragma unroll
        for (int j = 0; j < 16; j++) { uacc[j] = 0.0f; vacc[j] = 0.0f; }
        gemm2<true>(uacc, vacc, AH0, AH1, AL0, AL1, B0, B1);
#pragma unroll
        for (int j = 0; j < 16; j++) {
            dotv[j] += uacc[j] * vacc[j];
            ssq[j]  += vacc[j] * vacc[j];
        }
        POS_LOOP( Uf[(i << 13) + (row << 7) + col] = uacc[idx]; )
        __syncthreads();          // A (and on last iter, W0/W1) dead
        sts_pf();                 // next A tile
        __syncthreads();
    }

    // ---- phase 2: h = silu([s|vnorm] @ W1^T + b1) ----
    cpa_w(W0_OFF, 2);   // G2: W1a
    cpa_w(W1_OFF, 3);   // G3: W1b
    CP_WAIT1();         // G2 landed (G3 flying)
    __syncthreads();
    float hacc[16];
#pragma unroll
    for (int j = 0; j < 16; j++) hacc[j] = 0.0f;
    gemm2<false>(hacc, hacc, AH0, AH1, AL0, AL1, B0, 0);   // A=scalar, W1a
    __syncthreads();    // A dead, W0 dead
    POS_LOOP( put_hl(Ah, Al, row * 136 + col, sqrtf(ssq[idx])); )   // A = vnorm
    cpa_w(W0_OFF, 4);   // G4: W2a
    CP_WAIT1();         // G3 landed (G4 flying)
    __syncthreads();
    gemm2<false>(hacc, hacc, AH0, AH1, AL0, AL1, B1, 0);   // W1b
    __syncthreads();    // A dead, W1 dead
    POS_LOOP(           // A = silu(h + b1)
        float x = hacc[idx] + __ldg(b1g + col);
        put_hl(Ah, Al, row * 136 + col, x / (1.0f + __expf(-x)));
    )
    cpa_w(W1_OFF, 5);   // G5: W2b
    CP_WAIT0();         // G4, G5 landed
    __syncthreads();

    // ---- phase 3: a,b (dual), then c ----
    float aacc[16], bacc[16];
#pragma unroll
    for (int j = 0; j < 16; j++) { aacc[j] = 0.0f; bacc[j] = 0.0f; }
    gemm2<true>(aacc, bacc, AH0, AH1, AL0, AL1, B0, B1);
    float av[16], bv[16];
    POS_LOOP(
        av[idx] = aacc[idx] + __ldg(b2g + col);
        bv[idx] = bacc[idx] + __ldg(b2g + 128 + col);
    )
    __syncthreads();    // W0 dead
    cpa_w(W0_OFF, 6);   // G6: W2c
    CP_WAIT0();
    __syncthreads();
    float cacc[16];
#pragma unroll
    for (int j = 0; j < 16; j++) cacc[j] = 0.0f;
    gemm2<false>(cacc, cacc, AH0, AH1, AL0, AL1, B0, 0);

    // ---- epilogue: direct global writes from fragment owners ----
    // delta_s = b + c*dot  (float2, 8B-aligned)
    {
        float* out_ds = out + (size_t)nrows * 384;
#pragma unroll
        for (int mt = 0; mt < 2; mt++)
#pragma unroll
            for (int nt = 0; nt < 2; nt++)
#pragma unroll
                for (int j2 = 0; j2 < 2; j2++) {
                    const int i0 = mt * 8 + nt * 4 + j2 * 2;
                    const int row = rbase + mt * 16 + j2 * 8;
                    const int c = cbase + nt * 8;
                    float c0 = cacc[i0]     + __ldg(b2g + 256 + c);
                    float c1 = cacc[i0 + 1] + __ldg(b2g + 256 + c + 1);
                    float2 d = make_float2(bv[i0] + c0 * dotv[i0],
                                           bv[i0 + 1] + c1 * dotv[i0 + 1]);
                    *(float2*)(out_ds + (size_t)(row0 + row) * 128 + c) = d;
                }
    }
    // delta_v = u (fp32) * a  (3x float2 per (row, col-pair))
#pragma unroll
    for (int mt = 0; mt < 2; mt++)
#pragma unroll
        for (int nt = 0; nt < 2; nt++)
#pragma unroll
            for (int j2 = 0; j2 < 2; j2++) {
                const int i0 = mt * 8 + nt * 4 + j2 * 2;
                const int row = rbase + mt * 16 + j2 * 8;
                const int c = cbase + nt * 8;
                float a0 = av[i0], a1 = av[i0 + 1];
                float u0c = Uf[(0 << 13) + (row << 7) + c];
                float u1c = Uf[(1 << 13) + (row << 7) + c];
                float u2c = Uf[(2 << 13) + (row << 7) + c];
                float u0d = Uf[(0 << 13) + (row << 7) + c + 1];
                float u1d = Uf[(1 << 13) + (row << 7) + c + 1];
                float u2d = Uf[(2 << 13) + (row << 7) + c + 1];
                float* op = out + (size_t)(row0 + row) * 384 + (size_t)c * 3;
                ((float2*)op)[0] = make_float2(u0c * a0, u1c * a0);
                ((float2*)op)[1] = make_float2(u2c * a0, u0d * a1);
                ((float2*)op)[2] = make_float2(u1d * a1, u2d * a1);
            }
#undef POS_LOOP
}

// ---------------------------------------------------------------------------
extern "C" void kernel_launch(void* const* d_in, const int* in_sizes, int n_in,
                              void* d_out, int out_size) {
    const float* vec = (const float*)d_in[0];  // [N, C, 3]
    const float* sca = (const float*)d_in[1];  // [N, C]
    const float* U   = (const float*)d_in[2];  // [C, C]
    const float* V   = (const float*)d_in[3];  // [C, C]
    const float* W1  = (const float*)d_in[4];  // [C, 2C]
    const float* b1  = (const float*)d_in[5];  // [C]
    const float* W2  = (const float*)d_in[6];  // [3C, C]
    const float* b2  = (const float*)d_in[7];  // [3C]
    float* out = (float*)d_out;

    int nrows = in_sizes[0] / 384;
    int nblocks = nrows / RB;

    prep_kernel<<<448, 256>>>(U, V, W1, W2);

    cudaFuncSetAttribute(update_mma_kernel,
                         cudaFuncAttributeMaxDynamicSharedMemorySize, SM_TOTAL);
    update_mma_kernel<<<nblocks, NT, SM_TOTAL>>>(vec, sca, b1, b2, out, nrows);
}

// round 15
// speedup vs baseline: 2.1437x; 1.3072x over previous
#include <cuda_runtime.h>
#include <cuda_fp16.h>
#include <math.h>
#include <stdint.h>

#define NT 512
#define RB 64

// smem byte offsets
#define AH_OFF   0          // A [64][136] fp16
#define W0_OFF   17408      // weight [128][136] fp16
#define W1_OFF   52224
#define UF_OFF   87040      // u fp32 [3][64][128] = 98304 B
#define SM_TOTAL 185344

// pre-rounded padded weights: 7 tiles of [128 n][136 k] fp16
// tiles: 0=U, 1=V, 2=W1[:, :128], 3=W1[:, 128:], 4..6=W2 row-chunks
__device__ __align__(16) __half g_wh[7 * 128 * 136];

__device__ __forceinline__ uint32_t s2u(const void* p) {
    uint32_t a;
    asm("{ .reg .u64 t; cvta.to.shared.u64 t, %1; cvt.u32.u64 %0, t; }" : "=r"(a) : "l"(p));
    return a;
}

#define LDSM4(d, a) \
    asm volatile("ldmatrix.sync.aligned.m8n8.x4.shared.b16 {%0,%1,%2,%3}, [%4];" \
                 : "=r"((d)[0]), "=r"((d)[1]), "=r"((d)[2]), "=r"((d)[3]) : "r"(a))

__device__ __forceinline__ void mma_16816(float* d, const uint32_t a[4],
                                          uint32_t b0, uint32_t b1) {
    asm volatile(
        "mma.sync.aligned.m16n8k16.row.col.f32.f16.f16.f32 "
        "{%0,%1,%2,%3}, {%4,%5,%6,%7}, {%8,%9}, {%0,%1,%2,%3};"
        : "+f"(d[0]), "+f"(d[1]), "+f"(d[2]), "+f"(d[3])
        : "r"(a[0]), "r"(a[1]), "r"(a[2]), "r"(a[3]), "r"(b0), "r"(b1));
}

__device__ __forceinline__ void cp16(uint32_t dst, const void* src) {
    asm volatile("cp.async.cg.shared.global [%0], [%1], 16;"
                 :: "r"(dst), "l"(src) : "memory");
}
#define CP_COMMIT() asm volatile("cp.async.commit_group;" ::: "memory")
#define CP_WAIT0()  asm volatile("cp.async.wait_group 0;" ::: "memory")
#define CP_WAIT1()  asm volatile("cp.async.wait_group 1;" ::: "memory")

// K=128 GEMM, single-pass fp16: acc0 (+)= A x B0 [, acc1 (+)= A x B1]
template <bool DUAL>
__device__ __forceinline__ void gemm1(float* acc0, float* acc1,
                                      uint32_t aH0, uint32_t aH1,
                                      uint32_t b0, uint32_t b1) {
#pragma unroll
    for (int k0 = 0; k0 < 128; k0 += 16) {
        const uint32_t ko = (uint32_t)k0 * 2;
        uint32_t fa[2][4], fb0[4];
        LDSM4(fa[0], aH0 + ko);
        LDSM4(fa[1], aH1 + ko);
        LDSM4(fb0, b0 + ko);
#pragma unroll
        for (int mt = 0; mt < 2; mt++)
#pragma unroll
            for (int nt = 0; nt < 2; nt++)
                mma_16816(acc0 + mt * 8 + nt * 4, fa[mt], fb0[nt * 2], fb0[nt * 2 + 1]);
        if (DUAL) {
            uint32_t fb1[4];
            LDSM4(fb1, b1 + ko);
#pragma unroll
            for (int mt = 0; mt < 2; mt++)
#pragma unroll
                for (int nt = 0; nt < 2; nt++)
                    mma_16816(acc1 + mt * 8 + nt * 4, fa[mt], fb1[nt * 2], fb1[nt * 2 + 1]);
        }
    }
}

// ---------------------------------------------------------------------------
__global__ void prep_kernel(const float* __restrict__ U, const float* __restrict__ V,
                            const float* __restrict__ W1, const float* __restrict__ W2) {
    int idx = blockIdx.x * blockDim.x + threadIdx.x;
    if (idx >= 7 * 16384) return;
    int t = idx >> 14;
    int n = (idx >> 7) & 127;
    int k = idx & 127;
    float val;
    if (t == 0)      val = U[n * 128 + k];
    else if (t == 1) val = V[n * 128 + k];
    else if (t == 2) val = W1[n * 256 + k];
    else if (t == 3) val = W1[n * 256 + 128 + k];
    else             val = W2[((t - 4) * 128 + n) * 128 + k];
    g_wh[t * 17408 + n * 136 + k] = __float2half_rn(val);
}

// ---------------------------------------------------------------------------
__global__ __launch_bounds__(NT, 1)
void update_mma_kernel(const float* __restrict__ vec, const float* __restrict__ sca,
                       const float* __restrict__ b1g, const float* __restrict__ b2g,
                       float* __restrict__ out, int nrows) {
    extern __shared__ char sm[];
    const uint32_t smb = s2u(sm);
    __half* Ah = (__half*)(sm + AH_OFF);
    float*  Uf = (float*)(sm + UF_OFF);  // u fp32 [3][64][128]

    const int tid = threadIdx.x;
    const int lane = tid & 31;
    const int w = tid >> 5;
    const int wm = w & 1;    // M band (0/1)
    const int wn = w >> 1;   // N band (0..7)
    const int row0 = blockIdx.x * RB;

    // ldmatrix per-thread byte offsets (within a [.][136]-half region)
    const uint32_t aoff0 = ((wm * 32 + (lane & 7) + ((lane >> 3) & 1) * 8) * 136
                            + ((lane >> 4) & 1) * 8) * 2;
    const uint32_t aoff1 = aoff0 + 16 * 136 * 2;
    const uint32_t boff  = ((wn * 16 + ((lane >> 4) & 1) * 8 + (lane & 7)) * 136
                            + ((lane >> 3) & 1) * 8) * 2;

    const uint32_t AH0 = smb + AH_OFF + aoff0, AH1 = smb + AH_OFF + aoff1;
    const uint32_t B0 = smb + W0_OFF + boff, B1 = smb + W1_OFF + boff;

    // fragment ownership bases
    const int rbase = wm * 32 + (lane >> 2);
    const int cbase = wn * 16 + (lane & 3) * 2;

#define POS_LOOP(body) \
    _Pragma("unroll") for (int mt = 0; mt < 2; mt++) \
    _Pragma("unroll") for (int nt = 0; nt < 2; nt++) \
    _Pragma("unroll") for (int jj = 0; jj < 4; jj++) { \
        const int idx = mt * 8 + nt * 4 + jj; \
        const int row = rbase + mt * 16 + (jj >> 1) * 8; \
        const int col = cbase + nt * 8 + (jj & 1); \
        body \
    }

    // weight tile t (34816 B) -> region, one cp.async group
    auto cpa_w = [&](uint32_t dstOff, int t) {
        const uint4* sh = (const uint4*)(g_wh + t * 17408);
        for (int i = tid; i < 2176; i += NT) cp16(smb + dstOff + i * 16, sh + i);
        CP_COMMIT();
    };

    float pf[16];
    auto prefetch_vec = [&](int i) {
#pragma unroll
        for (int q = 0; q < 16; q++) {
            int e = tid + q * NT;
            int r = e >> 7, c = e & 127;
            pf[q] = __ldg(vec + (size_t)(row0 + r) * 384 + c * 3 + i);
        }
    };
    auto prefetch_sca = [&]() {
#pragma unroll
        for (int q = 0; q < 16; q++) {
            int e = tid + q * NT;
            int r = e >> 7, c = e & 127;
            pf[q] = __ldg(sca + (size_t)(row0 + r) * 128 + c);
        }
    };
    auto sts_pf = [&]() {
#pragma unroll
        for (int q = 0; q < 16; q++) {
            int e = tid + q * NT;
            int r = e >> 7, c = e & 127;
            Ah[r * 136 + c] = __float2half_rn(pf[q]);
        }
    };

    // ---- init: weights U,V in flight; X0 staged ----
    prefetch_vec(0);
    cpa_w(W0_OFF, 0);   // G0: U
    cpa_w(W1_OFF, 1);   // G1: V
    sts_pf();
    CP_WAIT0();
    __syncthreads();

    // ---- phase 1: u,v per component (dual); fold; u -> Uf (fp32) ----
    float dotv[16], ssq[16];
#pragma unroll
    for (int j = 0; j < 16; j++) { dotv[j] = 0.0f; ssq[j] = 1e-8f; }

    for (int i = 0; i < 3; i++) {
        if (i < 2) prefetch_vec(i + 1);
        else       prefetch_sca();
        float uacc[16], vacc[16];
#pragma unroll
        for (int j = 0; j < 16; j++) { uacc[j] = 0.0f; vacc[j] = 0.0f; }
        gemm1<true>(uacc, vacc, AH0, AH1, B0, B1);
#pragma unroll
        for (int j = 0; j < 16; j++) {
            dotv[j] += uacc[j] * vacc[j];
            ssq[j]  += vacc[j] * vacc[j];
        }
        POS_LOOP( Uf[(i << 13) + (row << 7) + col] = uacc[idx]; )
        __syncthreads();          // A (and on last iter, W0/W1) dead
        sts_pf();                 // next A tile
        __syncthreads();
    }

    // ---- phase 2: h = silu([s|vnorm] @ W1^T + b1) ----
    cpa_w(W0_OFF, 2);   // G2: W1a
    cpa_w(W1_OFF, 3);   // G3: W1b
    CP_WAIT1();         // G2 landed (G3 flying)
    __syncthreads();
    float hacc[16];
#pragma unroll
    for (int j = 0; j < 16; j++) hacc[j] = 0.0f;
    gemm1<false>(hacc, hacc, AH0, AH1, B0, 0);   // A=scalar, W1a
    __syncthreads();    // A dead, W0 dead
    POS_LOOP( Ah[row * 136 + col] = __float2half_rn(sqrtf(ssq[idx])); )  // A = vnorm
    cpa_w(W0_OFF, 4);   // G4: W2a
    CP_WAIT1();         // G3 landed (G4 flying)
    __syncthreads();
    gemm1<false>(hacc, hacc, AH0, AH1, B1, 0);   // W1b
    __syncthreads();    // A dead, W1 dead
    POS_LOOP(           // A = silu(h + b1)
        float x = hacc[idx] + __ldg(b1g + col);
        Ah[row * 136 + col] = __float2half_rn(x / (1.0f + __expf(-x)));
    )
    cpa_w(W1_OFF, 5);   // G5: W2b
    CP_WAIT0();         // G4, G5 landed
    __syncthreads();

    // ---- phase 3: a,b (dual), then c ----
    float aacc[16], bacc[16];
#pragma unroll
    for (int j = 0; j < 16; j++) { aacc[j] = 0.0f; bacc[j] = 0.0f; }
    gemm1<true>(aacc, bacc, AH0, AH1, B0, B1);
    float av[16], bv[16];
    POS_LOOP(
        av[idx] = aacc[idx] + __ldg(b2g + col);
        bv[idx] = bacc[idx] + __ldg(b2g + 128 + col);
    )
    __syncthreads();    // W0 dead
    cpa_w(W0_OFF, 6);   // G6: W2c
    CP_WAIT0();
    __syncthreads();
    float cacc[16];
#pragma unroll
    for (int j = 0; j < 16; j++) cacc[j] = 0.0f;
    gemm1<false>(cacc, cacc, AH0, AH1, B0, 0);

    // ---- epilogue: direct global writes from fragment owners ----
    // delta_s = b + c*dot  (float2, 8B-aligned)
    {
        float* out_ds = out + (size_t)nrows * 384;
#pragma unroll
        for (int mt = 0; mt < 2; mt++)
#pragma unroll
            for (int nt = 0; nt < 2; nt++)
#pragma unroll
                for (int j2 = 0; j2 < 2; j2++) {
                    const int i0 = mt * 8 + nt * 4 + j2 * 2;
                    const int row = rbase + mt * 16 + j2 * 8;
                    const int c = cbase + nt * 8;
                    float c0 = cacc[i0]     + __ldg(b2g + 256 + c);
                    float c1 = cacc[i0 + 1] + __ldg(b2g + 256 + c + 1);
                    float2 d = make_float2(bv[i0] + c0 * dotv[i0],
                                           bv[i0 + 1] + c1 * dotv[i0 + 1]);
                    *(float2*)(out_ds + (size_t)(row0 + row) * 128 + c) = d;
                }
    }
    // delta_v = u (fp32) * a  (3x float2 per (row, col-pair))
#pragma unroll
    for (int mt = 0; mt < 2; mt++)
#pragma unroll
        for (int nt = 0; nt < 2; nt++)
#pragma unroll
            for (int j2 = 0; j2 < 2; j2++) {
                const int i0 = mt * 8 + nt * 4 + j2 * 2;
                const int row = rbase + mt * 16 + j2 * 8;
                const int c = cbase + nt * 8;
                float a0 = av[i0], a1 = av[i0 + 1];
                float u0c = Uf[(0 << 13) + (row << 7) + c];
                float u1c = Uf[(1 << 13) + (row << 7) + c];
                float u2c = Uf[(2 << 13) + (row << 7) + c];
                float u0d = Uf[(0 << 13) + (row << 7) + c + 1];
                float u1d = Uf[(1 << 13) + (row << 7) + c + 1];
                float u2d = Uf[(2 << 13) + (row << 7) + c + 1];
                float* op = out + (size_t)(row0 + row) * 384 + (size_t)c * 3;
                ((float2*)op)[0] = make_float2(u0c * a0, u1c * a0);
                ((float2*)op)[1] = make_float2(u2c * a0, u0d * a1);
                ((float2*)op)[2] = make_float2(u1d * a1, u2d * a1);
            }
#undef POS_LOOP
}

// ---------------------------------------------------------------------------
extern "C" void kernel_launch(void* const* d_in, const int* in_sizes, int n_in,
                              void* d_out, int out_size) {
    const float* vec = (const float*)d_in[0];  // [N, C, 3]
    const float* sca = (const float*)d_in[1];  // [N, C]
    const float* U   = (const float*)d_in[2];  // [C, C]
    const float* V   = (const float*)d_in[3];  // [C, C]
    const float* W1  = (const float*)d_in[4];  // [C, 2C]
    const float* b1  = (const float*)d_in[5];  // [C]
    const float* W2  = (const float*)d_in[6];  // [3C, C]
    const float* b2  = (const float*)d_in[7];  // [3C]
    float* out = (float*)d_out;

    int nrows = in_sizes[0] / 384;
    int nblocks = nrows / RB;

    prep_kernel<<<448, 256>>>(U, V, W1, W2);

    cudaFuncSetAttribute(update_mma_kernel,
                         cudaFuncAttributeMaxDynamicSharedMemorySize, SM_TOTAL);
    update_mma_kernel<<<nblocks, NT, SM_TOTAL>>>(vec, sca, b1, b2, out, nrows);
}